// round 3
// baseline (speedup 1.0000x reference)
#include <cuda_runtime.h>
#include <math.h>

// x: 4096x4096 fp32 = 16,777,216 elements -> 262,144 blocks of 64.
#define MAXB   262144
#define MAXW   (MAXB * 8)      // packed 4-bit codes: 8 u32 words per block
#define MAXGA  4096            // per-CTA min/max partials

__device__ float    g_scales[MAXB];
__device__ float    g_deq4[MAXB];      // per-block deq_scale * 0.25
__device__ unsigned g_codes[MAXW];     // 4-bit codes: lv(0..5) | sign<<3
__device__ float    g_pmin[MAXGA];
__device__ float    g_pmax[MAXGA];
__device__ float    g_smin;
__device__ float    g_ss;
__device__ int      g_cond;
__device__ unsigned g_ctr;             // last-CTA election counter (stays 0)

// Branchless insertion of v into descending top-5.
__device__ __forceinline__ void ins5(float v, float& t0, float& t1, float& t2,
                                     float& t3, float& t4) {
    float hi, lo;
    hi = fmaxf(t0, v); lo = fminf(t0, v); t0 = hi; v = lo;
    hi = fmaxf(t1, v); lo = fminf(t1, v); t1 = hi; v = lo;
    hi = fmaxf(t2, v); lo = fminf(t2, v); t2 = hi; v = lo;
    hi = fmaxf(t3, v); lo = fminf(t3, v); t3 = hi; v = lo;
    t4 = fmaxf(t4, v);
}

// 4-bit quant code for one element. Magnitude levels {0.75,1,1.5,2,3} are the
// 1-mantissa-bit fp32 grid: clamp |q| to [0.75,3], add 0x1FFFFF (round-half-
// down = positive argmin tie rule), exponent+msb gives level 1..5. Level 0 if
// |q| <= 0.375. Bit 3 = sign.
__device__ __forceinline__ unsigned code1(float x, float rs) {
    float q = __fmul_rn(x, rs);
    float a = fabsf(q);
    float m = fminf(fmaxf(a, 0.75f), 3.0f);
    unsigned lv = ((__float_as_uint(m) + 0x001FFFFFu) >> 22) - 0xFCu;  // 1..5
    lv = (a > 0.375f) ? lv : 0u;
    return lv | ((__float_as_uint(q) >> 28) & 8u);
}

// ---------------------------------------------------------------------------
// Pass 1: per-block 95th-percentile scale (4th & 5th largest |x| of 64) AND
// per-element 4-bit quantization codes. Last CTA reduces scale min/max.
// 128 threads/CTA, one 64-elem block per thread, smem-staged (stride-17 pad).
// ---------------------------------------------------------------------------
__global__ void __launch_bounds__(128) kP1(const float4* __restrict__ in4,
                                           int n4, int num_blocks) {
    __shared__ float4 sm[128 * 17];
    __shared__ float  rmin[128];
    __shared__ float  rmax[128];
    __shared__ int    s_last;

    const int tid = threadIdx.x;
    const long long base4 = (long long)blockIdx.x * 2048;

    #pragma unroll
    for (int k = 0; k < 16; k++) {
        int f = k * 128 + tid;
        long long g4 = base4 + f;
        float4 v = (g4 < (long long)n4) ? in4[g4] : make_float4(0.f, 0.f, 0.f, 0.f);
        sm[(f >> 4) * 17 + (f & 15)] = v;
    }
    __syncthreads();

    float t0 = 0.f, t1 = 0.f, t2 = 0.f, t3 = 0.f, t4 = 0.f;
    #pragma unroll
    for (int j = 0; j < 16; j++) {
        float4 v = sm[tid * 17 + j];
        ins5(fabsf(v.x), t0, t1, t2, t3, t4);
        ins5(fabsf(v.y), t0, t1, t2, t3, t4);
        ins5(fabsf(v.z), t0, t1, t2, t3, t4);
        ins5(fabsf(v.w), t0, t1, t2, t3, t4);
    }

    // jnp.quantile linear: index = fp32(0.95*63), frac = index - 59.
    // a[59] = 5th largest = t4, a[60] = 4th largest = t3.
    const float FRAC = 0.95f * 63.0f - 59.0f;
    const float OMF  = 1.0f - FRAC;
    float s = __fadd_rn(__fmul_rn(t4, OMF), __fmul_rn(t3, FRAC));
    s = fmaxf(s, 1e-8f);

    long long b = (long long)blockIdx.x * 128 + tid;
    bool valid = (b < (long long)num_blocks);

    if (valid) {
        g_scales[b] = s;
        float rs = __frcp_rn(s);
        unsigned pw[8];
        #pragma unroll
        for (int w = 0; w < 8; w++) {
            float4 v0 = sm[tid * 17 + 2 * w];
            float4 v1 = sm[tid * 17 + 2 * w + 1];
            pw[w] =  code1(v0.x, rs)        | (code1(v0.y, rs) << 4)
                  | (code1(v0.z, rs) << 8)  | (code1(v0.w, rs) << 12)
                  | (code1(v1.x, rs) << 16) | (code1(v1.y, rs) << 20)
                  | (code1(v1.z, rs) << 24) | (code1(v1.w, rs) << 28);
        }
        uint4* dst = (uint4*)&g_codes[(size_t)b * 8];
        dst[0] = make_uint4(pw[0], pw[1], pw[2], pw[3]);
        dst[1] = make_uint4(pw[4], pw[5], pw[6], pw[7]);
    }

    rmin[tid] = valid ? s : 3.402823466e38f;
    rmax[tid] = valid ? s : 0.0f;
    __syncthreads();
    #pragma unroll
    for (int off = 64; off > 0; off >>= 1) {
        if (tid < off) {
            rmin[tid] = fminf(rmin[tid], rmin[tid + off]);
            rmax[tid] = fmaxf(rmax[tid], rmax[tid + off]);
        }
        __syncthreads();
    }
    if (tid == 0) {
        __stcg(&g_pmin[blockIdx.x], rmin[0]);
        __stcg(&g_pmax[blockIdx.x], rmax[0]);
        __threadfence();
        s_last = (atomicAdd(&g_ctr, 1u) == gridDim.x - 1);
    }
    __syncthreads();

    if (s_last) {                       // CTA-uniform
        int np = gridDim.x;
        float mn = 3.402823466e38f, mx = 0.0f;
        for (int i = tid; i < np; i += 128) {
            mn = fminf(mn, __ldcg(&g_pmin[i]));
            mx = fmaxf(mx, __ldcg(&g_pmax[i]));
        }
        rmin[tid] = mn; rmax[tid] = mx;
        __syncthreads();
        #pragma unroll
        for (int off = 64; off > 0; off >>= 1) {
            if (tid < off) {
                rmin[tid] = fminf(rmin[tid], rmin[tid + off]);
                rmax[tid] = fmaxf(rmax[tid], rmax[tid + off]);
            }
            __syncthreads();
        }
        if (tid == 0) {
            float smin = rmin[0], smax = rmax[0];
            int cond = (smax > smin);
            g_smin = smin;
            g_cond = cond;
            g_ss = cond ? __fdiv_rn(__fsub_rn(smax, smin), 255.0f) : 1.0f;
            g_ctr = 0u;                 // reset for next graph replay
        }
    }
}

// ---------------------------------------------------------------------------
// kC: per-block 8-bit double-quant of scales -> deq_scale * 0.25.
// ---------------------------------------------------------------------------
__global__ void __launch_bounds__(256) kC(int num_blocks) {
    int b = blockIdx.x * 256 + threadIdx.x;
    if (b >= num_blocks) return;
    float s = g_scales[b];
    float qv = 0.0f;
    if (g_cond) {
        qv = rintf(__fdiv_rn(__fsub_rn(s, g_smin), g_ss));  // half-even = jnp.round
        qv = fminf(fmaxf(qv, 0.0f), 255.0f);
    }
    // deq = qv*ss (smin deliberately dropped, matches ref); *0.25 exact scaling
    g_deq4[b] = __fmul_rn(qv, g_ss) * 0.25f;
}

// ---------------------------------------------------------------------------
// Pass 2: decode codes -> output. Read 8 MB + 1 MB, write 64 MB.
// mag*4 in {0,3,4,6,8,12} packed as nibbles of an immediate.
// ---------------------------------------------------------------------------
__device__ __forceinline__ float dec1(unsigned nib, float dq4) {
    float mag4 = (float)((0x00C86430u >> ((nib & 7u) << 2)) & 0xFu);
    float v = __fmul_rn(mag4, dq4);
    return __uint_as_float(__float_as_uint(v) | ((nib & 8u) << 28));
}

__global__ void __launch_bounds__(256) kE(float4* __restrict__ out4, int n4) {
    const unsigned short* pc = (const unsigned short*)g_codes;
    int base = blockIdx.x * 1024 + threadIdx.x;
    #pragma unroll
    for (int k = 0; k < 4; k++) {
        int i = base + k * 256;
        if (i < n4) {
            float dq4 = g_deq4[i >> 4];
            unsigned p = pc[i];          // 4 nibbles = 4 elements
            float4 o;
            o.x = dec1(p,       dq4);
            o.y = dec1(p >> 4,  dq4);
            o.z = dec1(p >> 8,  dq4);
            o.w = dec1(p >> 12, dq4);
            __stcs(&out4[i], o);
        }
    }
}

// Scalar tail (n % 4 != 0) — not hit for 4096x4096.
__global__ void kEtail(float* __restrict__ out, int start, int n) {
    int i = start + blockIdx.x * blockDim.x + threadIdx.x;
    if (i >= n) return;
    const unsigned char* pc = (const unsigned char*)g_codes;
    unsigned byte = pc[i >> 1];
    unsigned nib = (i & 1) ? (byte >> 4) : (byte & 0xFu);
    out[i] = dec1(nib, g_deq4[i >> 6]);
}

extern "C" void kernel_launch(void* const* d_in, const int* in_sizes, int n_in,
                              void* d_out, int out_size) {
    const float* x = (const float*)d_in[0];
    float* out = (float*)d_out;
    int n = in_sizes[0];

    int num_blocks = (n + 63) >> 6;
    if (num_blocks > MAXB) num_blocks = MAXB;   // fixed shape fits

    int gridA = (num_blocks + 127) >> 7;        // 128 blocks per CTA
    int n4 = n >> 2;

    kP1<<<gridA, 128>>>((const float4*)x, n4, num_blocks);
    kC<<<(num_blocks + 255) >> 8, 256>>>(num_blocks);
    if (n4 > 0)
        kE<<<(n4 + 1023) >> 10, 256>>>((float4*)out, n4);
    int tail = n & 3;
    if (tail)
        kEtail<<<1, 32>>>(out, n4 << 2, n);
}

// round 5
// speedup vs baseline: 1.1005x; 1.1005x over previous
#include <cuda_runtime.h>
#include <math.h>

// x: 4096x4096 fp32 = 16,777,216 elements -> 262,144 blocks of 64.
#define MAXB   262144
#define MAXGA  4096

__device__ float  g_scales[MAXB];
__device__ float2 g_info2[MAXB];    // {1/s (RN), deq_scale}
__device__ float  g_pmin[MAXGA];
__device__ float  g_pmax[MAXGA];
__device__ float  g_smin;
__device__ float  g_ss;
__device__ int    g_cond;
__device__ unsigned g_ctr;          // last-CTA election (returns to 0 each run)

// Branchless insertion of v into descending top-5.
__device__ __forceinline__ void ins5(float v, float& t0, float& t1, float& t2,
                                     float& t3, float& t4) {
    float hi, lo;
    hi = fmaxf(t0, v); lo = fminf(t0, v); t0 = hi; v = lo;
    hi = fmaxf(t1, v); lo = fminf(t1, v); t1 = hi; v = lo;
    hi = fmaxf(t2, v); lo = fminf(t2, v); t2 = hi; v = lo;
    hi = fmaxf(t3, v); lo = fminf(t3, v); t3 = hi; v = lo;
    t4 = fmaxf(t4, v);
}

// ---------------------------------------------------------------------------
// Kernel A: per-block 95th-percentile scale (4th & 5th largest |x| of 64).
// 128 threads/CTA, one 64-elem block per thread. Data staged through smem in
// TWO chunks along the WITHIN-BLOCK column axis: chunk c holds f4 column
// indices [c*8, c*8+8) of all 128 blocks. Loads stay fully coalesced (warp =
// 4 contiguous 128B segments, 4 lines/LDG.128) and thread tid always reads
// rows of ITS OWN block tid (sm[tid*9+j]). 18.9 KB smem -> ~11 CTAs/SM so
// the alu-pipe (FMNMX) bottleneck gets the occupancy it needs.
// Last CTA also reduces scale min/max globally.
// ---------------------------------------------------------------------------
__global__ void __launch_bounds__(128) kA(const float4* __restrict__ in4,
                                          int n4, int num_blocks) {
    __shared__ float4 sm[128 * 9];     // 8 f4 per block-row, row stride 9
    __shared__ float  rmin[128];
    __shared__ float  rmax[128];
    __shared__ int    s_last;

    const int tid = threadIdx.x;
    const long long base4 = (long long)blockIdx.x * 2048;  // 128 blocks * 16 f4

    float t0 = 0.f, t1 = 0.f, t2 = 0.f, t3 = 0.f, t4 = 0.f;

    #pragma unroll
    for (int c = 0; c < 2; c++) {
        #pragma unroll
        for (int k = 0; k < 8; k++) {
            int f   = k * 128 + tid;       // 0..1023 within chunk
            int blk = f >> 3;              // block row 0..127
            int j   = f & 7;               // column within chunk
            long long g4 = base4 + (long long)blk * 16 + c * 8 + j;
            float4 v = (g4 < (long long)n4) ? in4[g4]
                                            : make_float4(0.f, 0.f, 0.f, 0.f);
            sm[blk * 9 + j] = v;
        }
        __syncthreads();
        #pragma unroll
        for (int j = 0; j < 8; j++) {
            float4 v = sm[tid * 9 + j];
            ins5(fabsf(v.x), t0, t1, t2, t3, t4);
            ins5(fabsf(v.y), t0, t1, t2, t3, t4);
            ins5(fabsf(v.z), t0, t1, t2, t3, t4);
            ins5(fabsf(v.w), t0, t1, t2, t3, t4);
        }
        __syncthreads();
    }

    // jnp.quantile linear: index = fp32(0.95*63), frac = index - 59.
    // a[59] = 5th largest = t4, a[60] = 4th largest = t3.
    const float FRAC = 0.95f * 63.0f - 59.0f;
    const float OMF  = 1.0f - FRAC;
    float s = __fadd_rn(__fmul_rn(t4, OMF), __fmul_rn(t3, FRAC));
    s = fmaxf(s, 1e-8f);

    long long b = (long long)blockIdx.x * 128 + tid;
    bool valid = (b < (long long)num_blocks);
    if (valid) g_scales[b] = s;

    rmin[tid] = valid ? s : 3.402823466e38f;
    rmax[tid] = valid ? s : 0.0f;
    __syncthreads();
    #pragma unroll
    for (int off = 64; off > 0; off >>= 1) {
        if (tid < off) {
            rmin[tid] = fminf(rmin[tid], rmin[tid + off]);
            rmax[tid] = fmaxf(rmax[tid], rmax[tid + off]);
        }
        __syncthreads();
    }
    if (tid == 0) {
        __stcg(&g_pmin[blockIdx.x], rmin[0]);
        __stcg(&g_pmax[blockIdx.x], rmax[0]);
        __threadfence();
        s_last = (atomicAdd(&g_ctr, 1u) == gridDim.x - 1);
    }
    __syncthreads();

    if (s_last) {                      // CTA-uniform
        int np = gridDim.x;
        float mn = 3.402823466e38f, mx = 0.0f;
        for (int i = tid; i < np; i += 128) {
            mn = fminf(mn, __ldcg(&g_pmin[i]));
            mx = fmaxf(mx, __ldcg(&g_pmax[i]));
        }
        rmin[tid] = mn; rmax[tid] = mx;
        __syncthreads();
        #pragma unroll
        for (int off = 64; off > 0; off >>= 1) {
            if (tid < off) {
                rmin[tid] = fminf(rmin[tid], rmin[tid + off]);
                rmax[tid] = fmaxf(rmax[tid], rmax[tid + off]);
            }
            __syncthreads();
        }
        if (tid == 0) {
            float smin = rmin[0], smax = rmax[0];
            int cond = (smax > smin);
            g_smin = smin;
            g_cond = cond;
            g_ss = cond ? __fdiv_rn(__fsub_rn(smax, smin), 255.0f) : 1.0f;
            g_ctr = 0u;                // reset for next graph replay
        }
    }
}

// ---------------------------------------------------------------------------
// Kernel C: per-block finalize — 8-bit double-quant of scale + RN reciprocal.
// ---------------------------------------------------------------------------
__global__ void __launch_bounds__(256) kC(int num_blocks) {
    int b = blockIdx.x * 256 + threadIdx.x;
    if (b >= num_blocks) return;
    float s = g_scales[b];
    float qv = 0.0f;
    if (g_cond) {
        qv = rintf(__fdiv_rn(__fsub_rn(s, g_smin), g_ss)); // half-even = jnp.round
        qv = fminf(fmaxf(qv, 0.0f), 255.0f);
    }
    float deq = __fmul_rn(qv, g_ss);  // smin deliberately dropped (matches ref)
    float r   = __frcp_rn(s);
    g_info2[b] = make_float2(r, deq);
}

// ---------------------------------------------------------------------------
// Kernel D: quant+dequant in one read of x. 8 instrs/element via fp32
// bit-grid rounding: magnitude levels {0.75,1,1.5,2,3} are the 1-mantissa-bit
// fp32 grid -> clamp |q| to [0.75,3], +0x1FFFFF (round-half-down = positive
// argmin tie rule), mask. Zero level via |q|>0.375. Sign via LOP3.
// ---------------------------------------------------------------------------
__device__ __forceinline__ float qd1(float x, float r, float deq) {
    float q = __fmul_rn(x, r);
    float a = fabsf(q);
    float m = fminf(fmaxf(a, 0.75f), 3.0f);
    unsigned u = __float_as_uint(m) + 0x001FFFFFu;
    u &= 0xFFC00000u;
    float mag = (a > 0.375f) ? __uint_as_float(u) : 0.0f;
    float v = __fmul_rn(mag, deq);
    return __uint_as_float(__float_as_uint(v) |
                           (__float_as_uint(q) & 0x80000000u));
}

__global__ void __launch_bounds__(256) kD(const float4* __restrict__ in4,
                                          float4* __restrict__ out4, int n4) {
    int base = blockIdx.x * 1024 + threadIdx.x;
    #pragma unroll
    for (int k = 0; k < 4; k++) {
        int i = base + k * 256;
        if (i < n4) {
            int b = i >> 4;                 // 16 float4 per 64-elem block
            float2 nfo = g_info2[b];        // broadcast across 16 threads
            float4 x = in4[i];
            float4 o;
            o.x = qd1(x.x, nfo.x, nfo.y);
            o.y = qd1(x.y, nfo.x, nfo.y);
            o.z = qd1(x.z, nfo.x, nfo.y);
            o.w = qd1(x.w, nfo.x, nfo.y);
            __stcs(&out4[i], o);            // stream out: keep x resident in L2
        }
    }
}

// Scalar tail (n % 4 != 0) — not hit for 4096x4096.
__global__ void kDtail(const float* __restrict__ in, float* __restrict__ out,
                       int start, int n) {
    int i = start + blockIdx.x * blockDim.x + threadIdx.x;
    if (i >= n) return;
    int b = i >> 6;
    float2 nfo = g_info2[b];
    out[i] = qd1(in[i], nfo.x, nfo.y);
}

extern "C" void kernel_launch(void* const* d_in, const int* in_sizes, int n_in,
                              void* d_out, int out_size) {
    const float* x = (const float*)d_in[0];
    float* out = (float*)d_out;
    int n = in_sizes[0];

    int num_blocks = (n + 63) >> 6;
    if (num_blocks > MAXB) num_blocks = MAXB;   // fixed shape fits

    int gridA = (num_blocks + 127) >> 7;        // 128 blocks per CTA
    int n4 = n >> 2;

    kA<<<gridA, 128>>>((const float4*)x, n4, num_blocks);
    kC<<<(num_blocks + 255) >> 8, 256>>>(num_blocks);
    if (n4 > 0)
        kD<<<(n4 + 1023) >> 10, 256>>>((const float4*)x, (float4*)out, n4);
    int tail = n & 3;
    if (tail)
        kDtail<<<1, 32>>>(x, out, n4 << 2, n);
}